// round 15
// baseline (speedup 1.0000x reference)
#include <cuda_runtime.h>
#include <stdint.h>
#include <math.h>

#define BS   8
#define CCH  256
#define NND  9216     // H*W
#define EED  9215     // N-1 edges
#define EEDP 9216     // padded
#define ZETA 0.01f

#define CPB  16               // channels per dist block
#define GQ   (CCH/CPB)        // 16 groups per batch
#define TCH  2                // channels per tile step
#define NSTEP (CPB/TCH)       // 8 tile steps
#define MAXD 511
#define NT   1024
#define EPT  9                // ceil(EED/NT)
#define NCHUNK (NND/NT)       // 9
#define GRID (BS*GQ + 2*BS)   // 128 dist + 16 pass = 144 (<=148, co-resident)

// static device scratch (zero-init at load; counters/flags self-resetting)
__device__ float g_sum[(size_t)BS * EED];        // per-edge squared dist
__device__ float g_Z[(size_t)BS * NND];          // G field (denominator)
__device__ int   g_done[BS];                     // dist blocks finished
__device__ int   g_flagW[BS];                    // F-block done reading g_sum
__device__ int   g_flagZ[BS];                    // Z published

extern __shared__ float dyn_smem[];

__device__ __forceinline__ void cp_async16(uint32_t saddr, const void* gptr) {
    asm volatile("cp.async.cg.shared.global [%0], [%1], 16;\n"
                 :: "r"(saddr), "l"(gptr));
}
__device__ __forceinline__ void cp_commit() {
    asm volatile("cp.async.commit_group;\n");
}
template <int N>
__device__ __forceinline__ void cp_wait() {
    asm volatile("cp.async.wait_group %0;\n" :: "n"(N));
}

// ---------------------------------------------------------------------------
// Dist role: blocks 0..127 (unchanged).
// ---------------------------------------------------------------------------
__device__ void dist_role(const float* __restrict__ emb,
                          const int*   __restrict__ tree, int id) {
    float* buf0 = dyn_smem;
    float* buf1 = dyn_smem + TCH * NND;
    const int b   = id / GQ;
    const int g   = id % GQ;
    const int tid = threadIdx.x;

    const float* base = emb + ((size_t)b * CCH + (size_t)g * CPB) * NND;
    uint32_t s0 = (uint32_t)__cvta_generic_to_shared(buf0);
    uint32_t s1 = (uint32_t)__cvta_generic_to_shared(buf1);
    const int WORDS = TCH * NND / 4;

    for (int i = tid; i < WORDS; i += NT)
        cp_async16(s0 + i * 16, base + i * 4);
    cp_commit();

    const int2* tr2 = (const int2*)(tree + (size_t)b * EED * 2);
    int2 ed[EPT];
    float acc[EPT];
#pragma unroll
    for (int k = 0; k < EPT; k++) {
        int e = tid + k * NT;
        ed[k]  = (e < EED) ? tr2[e] : make_int2(0, 0);
        acc[k] = 0.f;
    }

    for (int t = 0; t < NSTEP; t++) {
        if (t + 1 < NSTEP) {
            uint32_t dst = (t & 1) ? s0 : s1;
            const float* srcp = base + (size_t)(t + 1) * TCH * NND;
            for (int i = tid; i < WORDS; i += NT)
                cp_async16(dst + i * 16, srcp + i * 4);
            cp_commit();
            cp_wait<1>();
        } else {
            cp_wait<0>();
        }
        __syncthreads();
        const float* cur = (t & 1) ? buf1 : buf0;
#pragma unroll
        for (int k = 0; k < EPT; k++) {
            float a0 = cur[ed[k].x];
            float b0 = cur[ed[k].y];
            float a1 = cur[NND + ed[k].x];
            float b1 = cur[NND + ed[k].y];
            float d0 = a0 - b0, d1 = a1 - b1;
            acc[k] += d0 * d0 + d1 * d1;
        }
        __syncthreads();
    }

    float* sp = g_sum + (size_t)b * EED;
#pragma unroll
    for (int k = 0; k < EPT; k++) {
        int e = tid + k * NT;
        if (e < EED) atomicAdd(sp + e, acc[k]);
    }

    __threadfence();
    __syncthreads();
    if (tid == 0) atomicAdd(&g_done[b], 1);
}

// ---------------------------------------------------------------------------
// Pass role: blocks 128..143 = (batch, field). Own prologue (overlapped with
// dist), spin on g_done, W-fill, level-loop UP pass, then DOWN pass via
// chunked affine parent-walk (9 barriers instead of ~30 level steps).
// smem: S f[NND] | ST int2[EEDP] (-> par i[NND] + F f[NND]) | W f[EEDP] |
//       wnode f[NND]
// ---------------------------------------------------------------------------
__device__ void pass_role(const float* __restrict__ fin,
                          const int*   __restrict__ tree,
                          float*       __restrict__ out,
                          int b, int which) {
    const int tid = threadIdx.x;
    const int wid = tid >> 5;
    const int lid = tid & 31;

    char*  smbase = (char*)dyn_smem;
    float* S     = (float*)smbase;
    int2*  ST    = (int2*)(smbase + (size_t)NND * 4);
    float* W     = (float*)(smbase + (size_t)NND * 4 + (size_t)EEDP * 8);
    float* wnode = (float*)(smbase + (size_t)NND * 4 + (size_t)EEDP * 12);
    int*   par   = (int*)smbase;                                 // prologue
    int*   dep   = (int*)(smbase + (size_t)NND * 4 + (size_t)EEDP * 8);
    // down pass reuses ST region:
    int*   par2  = (int*)(smbase + (size_t)NND * 4);
    float* F     = (float*)(smbase + (size_t)NND * 8);

    __shared__ int hist[MAXD + 1];
    __shared__ int lvlo[MAXD + 2];
    __shared__ int warpsum[16];
    __shared__ int s_maxLvl, s_bad;

    const int2* tr2 = (const int2*)(tree + (size_t)b * EED * 2);

    // ================= prologue (tree-only, overlapped with dist) ==========
    if (tid == 0) { s_maxLvl = 1; s_bad = 0; par[0] = 0; dep[0] = 0; }
    int2 ed[EPT];
#pragma unroll
    for (int k = 0; k < EPT; k++) {
        int e = tid + k * NT;
        ed[k] = (e < EED) ? tr2[e] : make_int2(0, 0);
        if (e < EED) par[ed[k].y] = ed[k].x;
    }
    __syncthreads();

#pragma unroll 1
    for (int c = 0; c < NCHUNK; c++) {
        int i = c * NT + tid;
        if (i > 0) {
            int B = c * NT;
            int j = par[i], d = 1;
            while (j >= B && j > 0) { j = par[j]; d++; }
            dep[i] = d + dep[j];
        }
        __syncthreads();
    }

    for (int k = tid; k <= MAXD; k += NT) hist[k] = 0;
    __syncthreads();
    int myd[EPT];
#pragma unroll
    for (int k = 0; k < EPT; k++) {
        int e = tid + k * NT;
        if (e < EED) {
            int d = dep[ed[k].y];
            myd[k] = d > MAXD ? MAXD : d;
            atomicAdd(&hist[myd[k]], 1);
        } else myd[k] = 0;
    }
    __syncthreads();

    // 2-barrier block scan over 512 bins
    {
        int binv = 0, incl = 0, bin = 0;
        if (wid < 16) {
            bin  = wid * 32 + lid;
            binv = hist[bin];
            int v = binv;
#pragma unroll
            for (int off = 1; off < 32; off <<= 1) {
                int t = __shfl_up_sync(0xffffffffu, v, off);
                if (lid >= off) v += t;
            }
            if (lid == 31) warpsum[wid] = v;
            incl = v;
        }
        __syncthreads();
        if (wid == 0 && lid < 16) {
            int v = warpsum[lid];
#pragma unroll
            for (int off = 1; off < 16; off <<= 1) {
                int t = __shfl_up_sync(0xffffu, v, off);
                if (lid >= off) v += t;
            }
            warpsum[lid] = v;
        }
        __syncthreads();
        if (wid < 16) {
            incl += wid ? warpsum[wid - 1] : 0;
            lvlo[bin + 1] = incl;
            hist[bin] = incl - binv;          // exclusive cursor
            if (binv > 0)  atomicMax(&s_maxLvl, bin);
            if (binv > 32) atomicMax(&s_bad, bin);
        }
        if (tid == 0) lvlo[0] = 0;
        __syncthreads();
    }

    // scatter (s,t) into level-sorted smem ST
#pragma unroll
    for (int k = 0; k < EPT; k++) {
        int e = tid + k * NT;
        if (e < EED) {
            int pos = atomicAdd(&hist[myd[k]], 1);
            ST[pos] = ed[k];
        }
    }
    __syncthreads();   // dep (in W region) dead after this

    // init field S (overwrites par region)
    if (which == 0) {
        const float* fb = fin + (size_t)b * NND;
        for (int i = tid; i < NND; i += NT) S[i] = fb[i];
    } else {
        for (int i = tid; i < NND; i += NT) S[i] = 1.f;
    }

    // ================= wait for dist, then weights ==========================
    if (tid == 0) {
        while (atomicAdd(&g_done[b], 0) < GQ) __nanosleep(64);
        __threadfence();
    }
    __syncthreads();

    const float* sp = g_sum + (size_t)b * EED;
    for (int i = tid; i < EED; i += NT) {
        int t = ST[i].y;
        float w = __expf(-ZETA * __ldcg(sp + (t - 1)));
        W[i] = w;
        wnode[t] = w;
    }
    if (tid == 0) wnode[0] = 1.f;
    __syncthreads();

    if (which == 0 && tid == 0) {
        __threadfence();
        atomicExch(&g_flagW[b], 1);
    }

    const int maxLvl = s_maxLvl;
    const int bad    = s_bad;

    // ================= UP pass (level loop, R14 shape) ======================
    if (wid == 0 && maxLvl > bad) {
        int idx = lvlo[maxLvl] + lid;
        bool act = idx < lvlo[maxLvl + 1];
        int2 stc = make_int2(0, 0); float wc = 0.f;
        if (act) { stc = ST[idx]; wc = W[idx]; }
#pragma unroll 1
        for (int d = maxLvl; d > bad; --d) {
            bool actn = false; int2 stn = make_int2(0, 0); float wn = 0.f;
            if (d - 1 > bad) {
                int nidx = lvlo[d - 1] + lid;
                actn = nidx < lvlo[d];
                if (actn) { stn = ST[nidx]; wn = W[nidx]; }
            }
            if (act) atomicAdd(&S[stc.x], wc * S[stc.y]);
            __syncwarp();
            act = actn; stc = stn; wc = wn;
        }
    }
    __syncthreads();
    if (bad >= 1) {
        int beg = lvlo[bad], end = lvlo[bad + 1];
        bool act = beg + tid < end;
        int2 stc = make_int2(0, 0); float wc = 0.f;
        if (act) { stc = ST[beg + tid]; wc = W[beg + tid]; }
#pragma unroll 1
        for (int d = bad; d >= 1; --d) {
            int nbeg = 0, nend = 0; bool actn = false;
            int2 stn = make_int2(0, 0); float wn = 0.f;
            if (d > 1) {
                nbeg = lvlo[d - 1]; nend = lvlo[d];
                actn = nbeg + tid < nend;
                if (actn) { stn = ST[nbeg + tid]; wn = W[nbeg + tid]; }
            }
            if (act) atomicAdd(&S[stc.x], wc * S[stc.y]);
            for (int idx2 = beg + tid + NT; idx2 < end; idx2 += NT) {
                int2 st = ST[idx2];
                atomicAdd(&S[st.x], W[idx2] * S[st.y]);
            }
            __syncthreads();
            beg = nbeg; end = nend; act = actn; stc = stn; wc = wn;
        }
    }
    __syncthreads();   // up pass complete; ST/W dead

    // ================= DOWN pass: chunked affine parent-walk ===============
    // F_t = w_t * F_par + (1 - w_t^2) * S_t ; affine maps compose along the
    // root path. parent < child, so chunks in index order finalize F.
    // par2/F overwrite the dead ST region.
    if (tid == 0) { par2[0] = 0; }
    for (int t = 1 + tid; t < NND; t += NT) par2[t] = tr2[t - 1].x;
    if (tid == 0) F[0] = S[0];
    __syncthreads();

#pragma unroll 1
    for (int c = 0; c < NCHUNK; c++) {
        int i = c * NT + tid;
        if (i > 0) {
            int base = c * NT; if (base < 1) base = 1;
            float wi = wnode[i];
            float a  = wi;
            float bb = (1.f - wi * wi) * S[i];
            int j = par2[i];
            while (j >= base) {
                float wj = wnode[j];
                bb += a * ((1.f - wj * wj) * S[j]);
                a  *= wj;
                j = par2[j];
            }
            F[i] = a * F[j] + bb;
        }
        __syncthreads();
    }

    // ================= exchange + output + replay hygiene ===================
    if (which == 1) {
        float* zp = g_Z + (size_t)b * NND;
        for (int i = tid; i < NND; i += NT) zp[i] = F[i];
        __threadfence();
        __syncthreads();
        if (tid == 0) {
            atomicExch(&g_flagZ[b], 1);
            while (atomicAdd(&g_flagW[b], 0) == 0) __nanosleep(64);
            atomicExch(&g_flagW[b], 0);        // reset for next replay
        }
        __syncthreads();
        float* spw = g_sum + (size_t)b * EED;
        for (int e = tid; e < EED; e += NT) spw[e] = 0.f;
        if (tid == 0) atomicExch(&g_done[b], 0);   // reset for next replay
    } else {
        if (tid == 0) {
            while (atomicAdd(&g_flagZ[b], 0) == 0) __nanosleep(64);
            __threadfence();
            atomicExch(&g_flagZ[b], 0);        // reset for next replay
        }
        __syncthreads();
        const float* zp = g_Z + (size_t)b * NND;
        float* ob = out + (size_t)b * NND;
        for (int i = tid; i < NND; i += NT) ob[i] = F[i] / __ldcg(zp + i);
    }
}

// ---------------------------------------------------------------------------
__global__ void __launch_bounds__(NT, 1)
mega_kernel(const float* __restrict__ fin,
            const float* __restrict__ emb,
            const int*   __restrict__ tree,
            float*       __restrict__ out) {
    if (blockIdx.x < BS * GQ) {
        dist_role(emb, tree, blockIdx.x);
    } else {
        int r = blockIdx.x - BS * GQ;
        pass_role(fin, tree, out, r >> 1, r & 1);
    }
}

// ---------------------------------------------------------------------------
extern "C" void kernel_launch(void* const* d_in, const int* in_sizes, int n_in,
                              void* d_out, int out_size) {
    const float* f    = (const float*)d_in[0];   // feature_in [8,1,96,96]
    const float* emb  = (const float*)d_in[1];   // embed_in   [8,256,96,96]
    const int*   tree = (const int*)d_in[2];     // tree       [8,9215,2]
    float*       out  = (float*)d_out;           // [8,1,96,96]

    // S + (ST -> par+F) + W + wnode = 36 + 72 + 36 + 36 KB
    size_t smem = (size_t)NND * 4 + (size_t)EEDP * 8 + (size_t)EEDP * 4
                + (size_t)NND * 4;   // 184320 B
    cudaFuncSetAttribute(mega_kernel,
                         cudaFuncAttributeMaxDynamicSharedMemorySize,
                         (int)smem);
    mega_kernel<<<GRID, NT, smem>>>(f, emb, tree, out);
}

// round 16
// speedup vs baseline: 1.1744x; 1.1744x over previous
#include <cuda_runtime.h>
#include <stdint.h>
#include <math.h>

#define BS   8
#define CCH  256
#define NND  9216     // H*W
#define EED  9215     // N-1 edges
#define EEDP 9216     // padded
#define ZETA 0.01f

#define CPB  16               // channels per dist block
#define GQ   (CCH/CPB)        // 16 groups per batch
#define TCH  2                // channels per tile step
#define NSTEP (CPB/TCH)       // 8 tile steps
#define TILEB (TCH*NND*4)     // 73728 bytes per tile
#define MAXD 511
#define NT   1024
#define EPT  9                // ceil(EED/NT)
#define NCHUNK (NND/NT)       // 9
#define GRID (BS*GQ + 2*BS)   // 128 dist + 16 pass = 144 (<=148, co-resident)

// static device scratch (zero-init at load; counters/flags self-resetting)
__device__ float g_sum[(size_t)BS * EED];        // per-edge squared dist
__device__ float g_Z[(size_t)BS * NND];          // G field (denominator)
__device__ int   g_done[BS];                     // dist blocks finished
__device__ int   g_flagW[BS];                    // F-block done reading g_sum
__device__ int   g_flagZ[BS];                    // Z published

extern __shared__ float dyn_smem[];

__device__ __forceinline__ uint32_t smem_u32(const void* p) {
    return (uint32_t)__cvta_generic_to_shared(p);
}
__device__ __forceinline__ void mbar_init(uint32_t mbar, uint32_t cnt) {
    asm volatile("mbarrier.init.shared.b64 [%0], %1;" :: "r"(mbar), "r"(cnt)
                 : "memory");
}
__device__ __forceinline__ void mbar_expect_tx(uint32_t mbar, uint32_t tx) {
    asm volatile("mbarrier.arrive.expect_tx.shared.b64 _, [%0], %1;"
                 :: "r"(mbar), "r"(tx) : "memory");
}
__device__ __forceinline__ void bulk_g2s(uint32_t dst, const void* src,
                                         uint32_t bytes, uint32_t mbar) {
    asm volatile(
        "cp.async.bulk.shared::cta.global.mbarrier::complete_tx::bytes "
        "[%0], [%1], %2, [%3];"
        :: "r"(dst), "l"(src), "r"(bytes), "r"(mbar) : "memory");
}
__device__ __forceinline__ void mbar_wait(uint32_t mbar, uint32_t phase) {
    uint32_t done;
    asm volatile(
        "{\n\t.reg .pred p;\n\t"
        "mbarrier.try_wait.parity.acquire.cta.shared::cta.b64 p, [%1], %2;\n\t"
        "selp.b32 %0, 1, 0, p;\n\t}"
        : "=r"(done) : "r"(mbar), "r"(phase) : "memory");
    while (!done) {
        asm volatile(
            "{\n\t.reg .pred p;\n\t"
            "mbarrier.try_wait.parity.acquire.cta.shared::cta.b64 p, [%1], %2, 0x989680;\n\t"
            "selp.b32 %0, 1, 0, p;\n\t}"
            : "=r"(done) : "r"(mbar), "r"(phase) : "memory");
    }
}
__device__ __forceinline__ void fence_proxy_async_cta() {
    asm volatile("fence.proxy.async.shared::cta;" ::: "memory");
}

// ---------------------------------------------------------------------------
// Dist role: blocks 0..127. Bulk-TMA double-buffered tiles (one UBLKCP per
// 73.7 KB instead of 4608 LDGSTS — removes the 8 B/cy/SM issue bound);
// partials REDG'd into g_sum; signals done.
// ---------------------------------------------------------------------------
__device__ void dist_role(const float* __restrict__ emb,
                          const int*   __restrict__ tree, int id) {
    __shared__ __align__(8) uint64_t mbar_s[2];
    float* buf[2] = { dyn_smem, dyn_smem + TCH * NND };
    const int b   = id / GQ;
    const int g   = id % GQ;
    const int tid = threadIdx.x;

    const float* base = emb + ((size_t)b * CCH + (size_t)g * CPB) * NND;
    uint32_t mb[2] = { smem_u32(&mbar_s[0]), smem_u32(&mbar_s[1]) };
    uint32_t bufa[2] = { smem_u32(buf[0]), smem_u32(buf[1]) };

    if (tid == 0) {
        mbar_init(mb[0], 1);
        mbar_init(mb[1], 1);
        fence_proxy_async_cta();
    }
    __syncthreads();

    // issue tile 0
    if (tid == 0) {
        mbar_expect_tx(mb[0], TILEB);
        bulk_g2s(bufa[0], base, TILEB, mb[0]);
    }

    // cache this thread's edges in registers (overlaps tile-0 flight)
    const int2* tr2 = (const int2*)(tree + (size_t)b * EED * 2);
    int2 ed[EPT];
    float acc[EPT];
#pragma unroll
    for (int k = 0; k < EPT; k++) {
        int e = tid + k * NT;
        ed[k]  = (e < EED) ? tr2[e] : make_int2(0, 0);
        acc[k] = 0.f;
    }

    int ph0 = 0, ph1 = 0;
    for (int t = 0; t < NSTEP; t++) {
        if (t + 1 < NSTEP && tid == 0) {
            int nb = (t + 1) & 1;
            mbar_expect_tx(mb[nb], TILEB);
            bulk_g2s(bufa[nb], base + (size_t)(t + 1) * TCH * NND,
                     TILEB, mb[nb]);
        }
        if ((t & 1) == 0) { mbar_wait(mb[0], ph0); ph0 ^= 1; }
        else              { mbar_wait(mb[1], ph1); ph1 ^= 1; }

        const float* cur = buf[t & 1];
#pragma unroll
        for (int k = 0; k < EPT; k++) {
            float a0 = cur[ed[k].x];
            float b0 = cur[ed[k].y];
            float a1 = cur[NND + ed[k].x];
            float b1 = cur[NND + ed[k].y];
            float d0 = a0 - b0, d1 = a1 - b1;
            acc[k] += d0 * d0 + d1 * d1;
        }
        __syncthreads();   // all reads done before this buffer is re-issued
    }

    float* sp = g_sum + (size_t)b * EED;
#pragma unroll
    for (int k = 0; k < EPT; k++) {
        int e = tid + k * NT;
        if (e < EED) atomicAdd(sp + e, acc[k]);
    }

    __threadfence();
    __syncthreads();
    if (tid == 0) atomicAdd(&g_done[b], 1);
}

// ---------------------------------------------------------------------------
// Pass role (unchanged from R15): own prologue overlapped with dist, W-fill,
// level-loop UP pass, chunked affine parent-walk DOWN pass.
// smem: S f[NND] | ST int2[EEDP] (-> par i[NND] + F f[NND]) | W f[EEDP] |
//       wnode f[NND]
// ---------------------------------------------------------------------------
__device__ void pass_role(const float* __restrict__ fin,
                          const int*   __restrict__ tree,
                          float*       __restrict__ out,
                          int b, int which) {
    const int tid = threadIdx.x;
    const int wid = tid >> 5;
    const int lid = tid & 31;

    char*  smbase = (char*)dyn_smem;
    float* S     = (float*)smbase;
    int2*  ST    = (int2*)(smbase + (size_t)NND * 4);
    float* W     = (float*)(smbase + (size_t)NND * 4 + (size_t)EEDP * 8);
    float* wnode = (float*)(smbase + (size_t)NND * 4 + (size_t)EEDP * 12);
    int*   par   = (int*)smbase;                                 // prologue
    int*   dep   = (int*)(smbase + (size_t)NND * 4 + (size_t)EEDP * 8);
    int*   par2  = (int*)(smbase + (size_t)NND * 4);
    float* F     = (float*)(smbase + (size_t)NND * 8);

    __shared__ int hist[MAXD + 1];
    __shared__ int lvlo[MAXD + 2];
    __shared__ int warpsum[16];
    __shared__ int s_maxLvl, s_bad;

    const int2* tr2 = (const int2*)(tree + (size_t)b * EED * 2);

    // ================= prologue (tree-only, overlapped with dist) ==========
    if (tid == 0) { s_maxLvl = 1; s_bad = 0; par[0] = 0; dep[0] = 0; }
    int2 ed[EPT];
#pragma unroll
    for (int k = 0; k < EPT; k++) {
        int e = tid + k * NT;
        ed[k] = (e < EED) ? tr2[e] : make_int2(0, 0);
        if (e < EED) par[ed[k].y] = ed[k].x;
    }
    __syncthreads();

#pragma unroll 1
    for (int c = 0; c < NCHUNK; c++) {
        int i = c * NT + tid;
        if (i > 0) {
            int B = c * NT;
            int j = par[i], d = 1;
            while (j >= B && j > 0) { j = par[j]; d++; }
            dep[i] = d + dep[j];
        }
        __syncthreads();
    }

    for (int k = tid; k <= MAXD; k += NT) hist[k] = 0;
    __syncthreads();
    int myd[EPT];
#pragma unroll
    for (int k = 0; k < EPT; k++) {
        int e = tid + k * NT;
        if (e < EED) {
            int d = dep[ed[k].y];
            myd[k] = d > MAXD ? MAXD : d;
            atomicAdd(&hist[myd[k]], 1);
        } else myd[k] = 0;
    }
    __syncthreads();

    // 2-barrier block scan over 512 bins
    {
        int binv = 0, incl = 0, bin = 0;
        if (wid < 16) {
            bin  = wid * 32 + lid;
            binv = hist[bin];
            int v = binv;
#pragma unroll
            for (int off = 1; off < 32; off <<= 1) {
                int t = __shfl_up_sync(0xffffffffu, v, off);
                if (lid >= off) v += t;
            }
            if (lid == 31) warpsum[wid] = v;
            incl = v;
        }
        __syncthreads();
        if (wid == 0 && lid < 16) {
            int v = warpsum[lid];
#pragma unroll
            for (int off = 1; off < 16; off <<= 1) {
                int t = __shfl_up_sync(0xffffu, v, off);
                if (lid >= off) v += t;
            }
            warpsum[lid] = v;
        }
        __syncthreads();
        if (wid < 16) {
            incl += wid ? warpsum[wid - 1] : 0;
            lvlo[bin + 1] = incl;
            hist[bin] = incl - binv;          // exclusive cursor
            if (binv > 0)  atomicMax(&s_maxLvl, bin);
            if (binv > 32) atomicMax(&s_bad, bin);
        }
        if (tid == 0) lvlo[0] = 0;
        __syncthreads();
    }

    // scatter (s,t) into level-sorted smem ST
#pragma unroll
    for (int k = 0; k < EPT; k++) {
        int e = tid + k * NT;
        if (e < EED) {
            int pos = atomicAdd(&hist[myd[k]], 1);
            ST[pos] = ed[k];
        }
    }
    __syncthreads();   // dep (in W region) dead after this

    // init field S (overwrites par region)
    if (which == 0) {
        const float* fb = fin + (size_t)b * NND;
        for (int i = tid; i < NND; i += NT) S[i] = fb[i];
    } else {
        for (int i = tid; i < NND; i += NT) S[i] = 1.f;
    }

    // ================= wait for dist, then weights ==========================
    if (tid == 0) {
        while (atomicAdd(&g_done[b], 0) < GQ) __nanosleep(64);
        __threadfence();
    }
    __syncthreads();

    const float* sp = g_sum + (size_t)b * EED;
    for (int i = tid; i < EED; i += NT) {
        int t = ST[i].y;
        float w = __expf(-ZETA * __ldcg(sp + (t - 1)));
        W[i] = w;
        wnode[t] = w;
    }
    if (tid == 0) wnode[0] = 1.f;
    __syncthreads();

    if (which == 0 && tid == 0) {
        __threadfence();
        atomicExch(&g_flagW[b], 1);
    }

    const int maxLvl = s_maxLvl;
    const int bad    = s_bad;

    // ================= UP pass (level loop) =================================
    if (wid == 0 && maxLvl > bad) {
        int idx = lvlo[maxLvl] + lid;
        bool act = idx < lvlo[maxLvl + 1];
        int2 stc = make_int2(0, 0); float wc = 0.f;
        if (act) { stc = ST[idx]; wc = W[idx]; }
#pragma unroll 1
        for (int d = maxLvl; d > bad; --d) {
            bool actn = false; int2 stn = make_int2(0, 0); float wn = 0.f;
            if (d - 1 > bad) {
                int nidx = lvlo[d - 1] + lid;
                actn = nidx < lvlo[d];
                if (actn) { stn = ST[nidx]; wn = W[nidx]; }
            }
            if (act) atomicAdd(&S[stc.x], wc * S[stc.y]);
            __syncwarp();
            act = actn; stc = stn; wc = wn;
        }
    }
    __syncthreads();
    if (bad >= 1) {
        int beg = lvlo[bad], end = lvlo[bad + 1];
        bool act = beg + tid < end;
        int2 stc = make_int2(0, 0); float wc = 0.f;
        if (act) { stc = ST[beg + tid]; wc = W[beg + tid]; }
#pragma unroll 1
        for (int d = bad; d >= 1; --d) {
            int nbeg = 0, nend = 0; bool actn = false;
            int2 stn = make_int2(0, 0); float wn = 0.f;
            if (d > 1) {
                nbeg = lvlo[d - 1]; nend = lvlo[d];
                actn = nbeg + tid < nend;
                if (actn) { stn = ST[nbeg + tid]; wn = W[nbeg + tid]; }
            }
            if (act) atomicAdd(&S[stc.x], wc * S[stc.y]);
            for (int idx2 = beg + tid + NT; idx2 < end; idx2 += NT) {
                int2 st = ST[idx2];
                atomicAdd(&S[st.x], W[idx2] * S[st.y]);
            }
            __syncthreads();
            beg = nbeg; end = nend; act = actn; stc = stn; wc = wn;
        }
    }
    __syncthreads();   // up pass complete; ST/W dead

    // ================= DOWN pass: chunked affine parent-walk ===============
    if (tid == 0) { par2[0] = 0; }
    for (int t = 1 + tid; t < NND; t += NT) par2[t] = tr2[t - 1].x;
    if (tid == 0) F[0] = S[0];
    __syncthreads();

#pragma unroll 1
    for (int c = 0; c < NCHUNK; c++) {
        int i = c * NT + tid;
        if (i > 0) {
            int base = c * NT; if (base < 1) base = 1;
            float wi = wnode[i];
            float a  = wi;
            float bb = (1.f - wi * wi) * S[i];
            int j = par2[i];
            while (j >= base) {
                float wj = wnode[j];
                bb += a * ((1.f - wj * wj) * S[j]);
                a  *= wj;
                j = par2[j];
            }
            F[i] = a * F[j] + bb;
        }
        __syncthreads();
    }

    // ================= exchange + output + replay hygiene ===================
    if (which == 1) {
        float* zp = g_Z + (size_t)b * NND;
        for (int i = tid; i < NND; i += NT) zp[i] = F[i];
        __threadfence();
        __syncthreads();
        if (tid == 0) {
            atomicExch(&g_flagZ[b], 1);
            while (atomicAdd(&g_flagW[b], 0) == 0) __nanosleep(64);
            atomicExch(&g_flagW[b], 0);        // reset for next replay
        }
        __syncthreads();
        float* spw = g_sum + (size_t)b * EED;
        for (int e = tid; e < EED; e += NT) spw[e] = 0.f;
        if (tid == 0) atomicExch(&g_done[b], 0);   // reset for next replay
    } else {
        if (tid == 0) {
            while (atomicAdd(&g_flagZ[b], 0) == 0) __nanosleep(64);
            __threadfence();
            atomicExch(&g_flagZ[b], 0);        // reset for next replay
        }
        __syncthreads();
        const float* zp = g_Z + (size_t)b * NND;
        float* ob = out + (size_t)b * NND;
        for (int i = tid; i < NND; i += NT) ob[i] = F[i] / __ldcg(zp + i);
    }
}

// ---------------------------------------------------------------------------
__global__ void __launch_bounds__(NT, 1)
mega_kernel(const float* __restrict__ fin,
            const float* __restrict__ emb,
            const int*   __restrict__ tree,
            float*       __restrict__ out) {
    if (blockIdx.x < BS * GQ) {
        dist_role(emb, tree, blockIdx.x);
    } else {
        int r = blockIdx.x - BS * GQ;
        pass_role(fin, tree, out, r >> 1, r & 1);
    }
}

// ---------------------------------------------------------------------------
extern "C" void kernel_launch(void* const* d_in, const int* in_sizes, int n_in,
                              void* d_out, int out_size) {
    const float* f    = (const float*)d_in[0];   // feature_in [8,1,96,96]
    const float* emb  = (const float*)d_in[1];   // embed_in   [8,256,96,96]
    const int*   tree = (const int*)d_in[2];     // tree       [8,9215,2]
    float*       out  = (float*)d_out;           // [8,1,96,96]

    // S + (ST -> par+F) + W + wnode = 36 + 72 + 36 + 36 KB
    size_t smem = (size_t)NND * 4 + (size_t)EEDP * 8 + (size_t)EEDP * 4
                + (size_t)NND * 4;   // 184320 B
    cudaFuncSetAttribute(mega_kernel,
                         cudaFuncAttributeMaxDynamicSharedMemorySize,
                         (int)smem);
    mega_kernel<<<GRID, NT, smem>>>(f, emb, tree, out);
}